// round 11
// baseline (speedup 1.0000x reference)
#include <cuda_runtime.h>
#include <cstdint>
#include <cstddef>

#define NJ 24
#define FRAMES_PER_SLAB 64
#define UNITS 128                               // (frame,pose) units per slab = threads
#define POSE_ROW_Q   37                         // f4 per padded pose row (36 data + 1 pad)
#define OFF_ROW_Q    18                         // f4 per off row
#define POSE_REGION_Q (UNITS * POSE_ROW_Q)      // 4736 f4
#define SLAB_Q       (POSE_REGION_Q + UNITS * OFF_ROW_Q)   // 7040 f4
#define SLAB_BYTES   (SLAB_Q * 16)              // 112640 B
#define SLAB_TX      (UNITS * (576 + 288))      // 110592 B actually copied
#define DYN_SMEM     (2 * SLAB_BYTES)           // 225280 B

__device__ float g_partials[16384];
__device__ unsigned int g_count = 0;

__device__ __forceinline__ float rsq(float x) {
    float y = __int_as_float(0x5f3759dfu - (__float_as_uint(x) >> 1));
    float hx = 0.5f * x;
    y = y * (1.5f - hx * y * y);
    y = y * (1.5f - hx * y * y);
    return y;
}

__device__ __forceinline__ void bulk_g2s(uint32_t dst, const void* src,
                                         uint32_t bytes, uint32_t mbar) {
    asm volatile(
        "cp.async.bulk.shared::cta.global.mbarrier::complete_tx::bytes [%0], [%1], %2, [%3];"
        :: "r"(dst), "l"(src), "r"(bytes), "r"(mbar) : "memory");
}
__device__ __forceinline__ void mbar_init(uint32_t mbar, uint32_t count) {
    asm volatile("mbarrier.init.shared.b64 [%0], %1;" :: "r"(mbar), "r"(count) : "memory");
}
__device__ __forceinline__ void mbar_expect_tx(uint32_t mbar, uint32_t tx) {
    asm volatile("mbarrier.arrive.expect_tx.shared.b64 _, [%0], %1;"
                 :: "r"(mbar), "r"(tx) : "memory");
}
__device__ __forceinline__ void mbar_wait(uint32_t mbar, uint32_t parity) {
    asm volatile(
        "{\n\t"
        ".reg .pred P;\n\t"
        "WL_%=:\n\t"
        "mbarrier.try_wait.parity.acquire.cta.shared::cta.b64 P, [%0], %1, 0x989680;\n\t"
        "@P bra.uni WD_%=;\n\t"
        "bra.uni WL_%=;\n\t"
        "WD_%=:\n\t"
        "}"
        :: "r"(mbar), "r"(parity) : "memory");
}

// Persistent kernel: gridDim.x = #SMs, 1 block/SM, 128 threads.
// Thread t = unit t: frame (t>>1) within slab, pose (t&1) (even=A, odd=B).
// Slabs of 64 frames stream through 2 smem buffers via per-row
// cp.async.bulk (576B pose rows padded to 592B in smem -> conflict-free
// LDS.128 at stride 37 quads; 288B off rows, N=2 tolerated).
__global__ void __launch_bounds__(128, 1)
ee_loss_kernel(const float* __restrict__ poseA, const float* __restrict__ poseB,
               const float* __restrict__ offA,  const float* __restrict__ offB,
               const float* __restrict__ tA,    const float* __restrict__ tB,
               float* __restrict__ out,
               int F, float inv_count)
{
    constexpr int PARENTS[NJ] = {-1,0,0,0,1,2,3,4,5,6,7,8,9,9,9,12,13,14,16,17,18,19,20,21};
    constexpr bool IS_EE[NJ] = {false,false,false,false,false,false,false,false,false,false,
                                true, true, false,false,false,true, false,false,false,false,
                                false,false,true, true};
    constexpr int EE_SLOT[NJ] = {-1,-1,-1,-1,-1,-1,-1,-1,-1,-1,
                                  0, 1,-1,-1,-1, 2,-1,-1,-1,-1,
                                 -1,-1, 3, 4};
    constexpr int END_SITES[5] = {10,11,15,22,23};

    extern __shared__ float4 dyn[];
    __shared__ uint64_t mbar_store[2];
    __shared__ float  s_iS[2][3];
    __shared__ float  s_c[2][15];
    __shared__ float  s_wsum[4];
    __shared__ bool   s_last;
    __shared__ double s_dsum[128];

    const int tid  = threadIdx.x;
    const int warp = tid >> 5;
    const int lane = tid & 31;
    const int pb   = tid & 1;
    const int grid = gridDim.x;
    const int bid  = blockIdx.x;

    const uint32_t dyn_u = (uint32_t)__cvta_generic_to_shared(dyn);
    uint32_t mb[2];
    mb[0] = (uint32_t)__cvta_generic_to_shared(&mbar_store[0]);
    mb[1] = (uint32_t)__cvta_generic_to_shared(&mbar_store[1]);

    if (tid == 0) {
        mbar_init(mb[0], 1);
        mbar_init(mb[1], 1);
        float mnA[3], mxA[3], mnB[3], mxB[3];
#pragma unroll
        for (int a = 0; a < 3; ++a) { mnA[a] = mxA[a] = tA[a]; mnB[a] = mxB[a] = tB[a]; }
#pragma unroll
        for (int j = 1; j < NJ; ++j) {
#pragma unroll
            for (int a = 0; a < 3; ++a) {
                const float va = tA[j * 3 + a];
                const float vb = tB[j * 3 + a];
                mnA[a] = fminf(mnA[a], va); mxA[a] = fmaxf(mxA[a], va);
                mnB[a] = fminf(mnB[a], vb); mxB[a] = fmaxf(mxB[a], vb);
            }
        }
#pragma unroll
        for (int a = 0; a < 3; ++a) {
            s_iS[0][a] = 1.0f / (mxA[a] - mnA[a]);
            s_iS[1][a] = 1.0f / (mxB[a] - mnB[a]);
        }
#pragma unroll
        for (int e = 0; e < 5; ++e) {
#pragma unroll
            for (int a = 0; a < 3; ++a) {
                s_c[0][e * 3 + a] = tA[END_SITES[e] * 3 + a] * s_iS[0][a];
                s_c[1][e * 3 + a] = tB[END_SITES[e] * 3 + a] * s_iS[1][a];
            }
        }
    }
    __syncthreads();

    const int S   = (F + FRAMES_PER_SLAB - 1) / FRAMES_PER_SLAB;   // total slabs
    const int nmy = (S > bid) ? ((S - 1 - bid) / grid + 1) : 0;    // my slab count

    // Issue all per-row bulk copies for slab s into buffer b.
    auto issue_slab = [&](int s, int b) {
        const int fr = min(s * FRAMES_PER_SLAB + (tid >> 1), F - 1);
        const float* psrc = (pb ? poseB : poseA) + (size_t)fr * 144;
        const float* osrc = (pb ? offB  : offA ) + (size_t)fr * 72;
        const uint32_t base = dyn_u + (uint32_t)(b * SLAB_BYTES);
        bulk_g2s(base + (uint32_t)(tid * (POSE_ROW_Q * 16)), psrc, 576, mb[b]);
        bulk_g2s(base + (uint32_t)(POSE_REGION_Q * 16 + tid * (OFF_ROW_Q * 16)),
                 osrc, 288, mb[b]);
    };

    // Prologue: prime both buffers.
    if (nmy > 0 && tid == 0) mbar_expect_tx(mb[0], SLAB_TX);
    if (nmy > 1 && tid == 0) mbar_expect_tx(mb[1], SLAB_TX);
    __syncthreads();
    if (nmy > 0) issue_slab(bid, 0);
    if (nmy > 1) issue_slab(bid + grid, 1);

    uint32_t ph[2] = {0u, 0u};
    float acc = 0.0f;

    for (int i = 0; i < nmy; ++i) {
        const int b = i & 1;
        mbar_wait(mb[b], ph[b]);
        ph[b] ^= 1u;

        const int s     = bid + i * grid;
        const int frame = s * FRAMES_PER_SLAB + (tid >> 1);
        const bool valid = (frame < F);

        const float4* __restrict__ prow = dyn + b * SLAB_Q + tid * POSE_ROW_Q;
        const float4* __restrict__ orow = dyn + b * SLAB_Q + POSE_REGION_Q + tid * OFF_ROW_Q;

        // ---- FK (R9 rolling-window body, reading smem) + folded loss ----
        float O[NJ][9];
        float P[NJ][3];
        float4 q0, q1, q2, u0, u1, u2;
#pragma unroll
        for (int j = 0; j < NJ; ++j) {
            if ((j & 1) == 0) {
                const int bb = (3 * j) / 2;
                q0 = prow[bb]; q1 = prow[bb + 1]; q2 = prow[bb + 2];
            }
            float a0, a1, a2, a3, a4, a5;
            if ((j & 1) == 0) { a0 = q0.x; a1 = q0.y; a2 = q0.z; a3 = q0.w; a4 = q1.x; a5 = q1.y; }
            else              { a0 = q1.z; a1 = q1.w; a2 = q2.x; a3 = q2.y; a4 = q2.z; a5 = q2.w; }

            if ((j & 3) == 0) {
                const int bb = (3 * j) / 4;
                u0 = orow[bb]; u1 = orow[bb + 1]; u2 = orow[bb + 2];
            }
            float ox, oy, oz;
            switch (j & 3) {
                case 0:  ox = u0.x; oy = u0.y; oz = u0.z; break;
                case 1:  ox = u0.w; oy = u1.x; oz = u1.y; break;
                case 2:  ox = u1.z; oy = u1.w; oz = u2.x; break;
                default: ox = u2.y; oy = u2.z; oz = u2.w; break;
            }

            float r0 = 0.f, r1 = 0.f, r2 = 0.f, r3 = 0.f, r4 = 0.f,
                  r5 = 0.f, r6 = 0.f, r7 = 0.f, r8 = 0.f;
            if (!IS_EE[j]) {
                const float n1 = a0 * a0 + a1 * a1 + a2 * a2;
                const float i1 = rsq(n1);
                r0 = a0 * i1; r1 = a1 * i1; r2 = a2 * i1;
                const float d  = r0 * a3 + r1 * a4 + r2 * a5;
                const float c0 = a3 - d * r0;
                const float c1 = a4 - d * r1;
                const float c2 = a5 - d * r2;
                const float n2 = c0 * c0 + c1 * c1 + c2 * c2;
                const float i2 = rsq(n2);
                r3 = c0 * i2; r4 = c1 * i2; r5 = c2 * i2;
                r6 = r1 * r5 - r2 * r4;
                r7 = r2 * r3 - r0 * r5;
                r8 = r0 * r4 - r1 * r3;
            }

            if (j == 0) {
                P[0][0] = ox; P[0][1] = oy; P[0][2] = oz;
                O[0][0] = r0; O[0][1] = r1; O[0][2] = r2;
                O[0][3] = r3; O[0][4] = r4; O[0][5] = r5;
                O[0][6] = r6; O[0][7] = r7; O[0][8] = r8;
            } else {
                const int p = PARENTS[j];
                const float px = O[p][0] * ox + O[p][1] * oy + O[p][2] * oz + P[p][0];
                const float py = O[p][3] * ox + O[p][4] * oy + O[p][5] * oz + P[p][1];
                const float pz = O[p][6] * ox + O[p][7] * oy + O[p][8] * oz + P[p][2];
                if (IS_EE[j]) {
                    const int sl = EE_SLOT[j];
                    const float v0 = px * s_iS[pb][0] - s_c[pb][sl * 3 + 0];
                    const float v1 = py * s_iS[pb][1] - s_c[pb][sl * 3 + 1];
                    const float v2 = pz * s_iS[pb][2] - s_c[pb][sl * 3 + 2];
                    const float w0 = __shfl_xor_sync(0xFFFFFFFFu, v0, 1);
                    const float w1 = __shfl_xor_sync(0xFFFFFFFFu, v1, 1);
                    const float w2 = __shfl_xor_sync(0xFFFFFFFFu, v2, 1);
                    if (valid) {
                        const float d0 = v0 - w0, d1 = v1 - w1, d2 = v2 - w2;
                        acc = fmaf(d0, d0, acc);
                        acc = fmaf(d1, d1, acc);
                        acc = fmaf(d2, d2, acc);
                    }
                } else {
                    P[j][0] = px; P[j][1] = py; P[j][2] = pz;
                    O[j][0] = O[p][0] * r0 + O[p][1] * r3 + O[p][2] * r6;
                    O[j][1] = O[p][0] * r1 + O[p][1] * r4 + O[p][2] * r7;
                    O[j][2] = O[p][0] * r2 + O[p][1] * r5 + O[p][2] * r8;
                    O[j][3] = O[p][3] * r0 + O[p][4] * r3 + O[p][5] * r6;
                    O[j][4] = O[p][3] * r1 + O[p][4] * r4 + O[p][5] * r7;
                    O[j][5] = O[p][3] * r2 + O[p][4] * r5 + O[p][5] * r8;
                    O[j][6] = O[p][6] * r0 + O[p][7] * r3 + O[p][8] * r6;
                    O[j][7] = O[p][6] * r1 + O[p][7] * r4 + O[p][8] * r7;
                    O[j][8] = O[p][6] * r2 + O[p][7] * r5 + O[p][8] * r8;
                }
            }
        }

        __syncthreads();            // all threads done reading buf b
        if (i + 2 < nmy) {
            if (tid == 0) mbar_expect_tx(mb[b], SLAB_TX);
            __syncthreads();        // expect_tx visible before any completion
            issue_slab(bid + (i + 2) * grid, b);
        }
    }

    // ---- deterministic in-block reduction ----
#pragma unroll
    for (int o = 16; o > 0; o >>= 1)
        acc += __shfl_xor_sync(0xFFFFFFFFu, acc, o);
    if (lane == 0) s_wsum[warp] = acc;
    __syncthreads();

    if (tid == 0) {
        g_partials[bid] = s_wsum[0] + s_wsum[1] + s_wsum[2] + s_wsum[3];
        __threadfence();
        const unsigned int done = atomicAdd(&g_count, 1u);
        s_last = (done == (unsigned int)(grid - 1));
    }
    __syncthreads();

    // Last block reduces all partials in a FIXED order -> deterministic.
    if (s_last) {
        double ds = 0.0;
        for (int i = tid; i < grid; i += 128)
            ds += (double)g_partials[i];
        s_dsum[tid] = ds;
        __syncthreads();
#pragma unroll
        for (int k = 64; k > 0; k >>= 1) {
            if (tid < k) s_dsum[tid] += s_dsum[tid + k];
            __syncthreads();
        }
        if (tid == 0) {
            out[0] = (float)(s_dsum[0] * (double)inv_count);
            g_count = 0;   // reset for next graph replay
        }
    }
}

extern "C" void kernel_launch(void* const* d_in, const int* in_sizes, int n_in,
                              void* d_out, int out_size)
{
    const float* poseA = (const float*)d_in[0];
    const float* poseB = (const float*)d_in[1];
    const float* offA  = (const float*)d_in[2];
    const float* offB  = (const float*)d_in[3];
    const float* tA    = (const float*)d_in[4];
    const float* tB    = (const float*)d_in[5];
    float* out = (float*)d_out;

    const int F = in_sizes[0] / (NJ * 6);
    int dev = 0, sms = 148;
    cudaGetDevice(&dev);
    cudaDeviceGetAttribute(&sms, cudaDevAttrMultiProcessorCount, dev);
    if (sms > 16384) sms = 16384;

    cudaFuncSetAttribute(ee_loss_kernel,
                         cudaFuncAttributeMaxDynamicSharedMemorySize, DYN_SMEM);

    // Each (frame,pose) pair contributes its squared diff twice -> extra /2.
    const float inv_count = 1.0f / ((float)F * 15.0f * 2.0f);
    ee_loss_kernel<<<sms, 128, DYN_SMEM>>>(poseA, poseB, offA, offB, tA, tB,
                                           out, F, inv_count);
}